// round 1
// baseline (speedup 1.0000x reference)
#include <cuda_runtime.h>
#include <math.h>

// Problem constants
#define BH   24          // B*H = 2*12
#define TT   2048        // sequence length
#define NN   256         // feature dim
#define CC   128         // chunk size
#define NCH  16          // number of chunks (TT/CC)

// ---------------- device scratch (static globals: sanctioned workaround) ----
__device__ float g_tabc[TT * (NN/2)];         // cos table [t][j]  (1 MB)
__device__ float g_tabs[TT * (NN/2)];         // sin table          (1 MB)
__device__ float g_QR[BH * TT * NN];          // roped Q (50 MB)
__device__ float g_KR[BH * TT * NN];          // roped K (50 MB)
__device__ float g_S [BH * NCH * NN * NN];    // chunk KV states -> exclusive prefix (100 MB)

// ---------------- kernel 1: RoPE phase tables -------------------------------
// freqs[n] = 1/theta^(q/N)/(2pi), theta=2^16, q=floor(n/2)*2 -> freq pair j:
// 2^(-j/8)/(2pi). Mimic reference fp32 rounding: f32 freq, f32 t*f, f32 frac.
__global__ void k_tables() {
    int id = blockIdx.x * blockDim.x + threadIdx.x;   // 262144 threads
    if (id >= TT * (NN/2)) return;
    int t = id >> 7;          // 0..2047
    int j = id & 127;         // pair index
    double fr_d = exp2(-(double)j / 8.0) / (2.0 * 3.14159265358979323846);
    float f32   = (float)fr_d;                 // reference stores freq in f32
    float ph    = (float)t * f32;              // f32 multiply like reference
    ph          = ph - floorf(ph);             // f32 frac (% 1.0)
    float ang   = ph * 6.28318530717958647692f; // f32 * f32(2pi)
    double angd = (double)ang;
    g_tabc[id] = (float)cos(angd);
    g_tabs[id] = (float)sin(angd);
}

// ---------------- kernel 2: apply RoPE to Q and K ---------------------------
__global__ void k_rope(const float* __restrict__ Q, const float* __restrict__ K) {
    int idx = blockIdx.x * blockDim.x + threadIdx.x;
    const int per = BH * TT * (NN/2);          // 6291456 pairs per tensor
    if (idx >= 2 * per) return;
    int which = idx >= per;
    int i = idx - which * per;
    int n2 = i & 127;
    int t  = (i >> 7) & 2047;
    int bh = i >> 18;
    int off = (bh * TT + t) * NN + 2 * n2;
    const float* src = which ? K : Q;
    float*       dst = which ? g_KR : g_QR;
    float2 v = *(const float2*)(src + off);
    float c = g_tabc[t * 128 + n2];
    float s = g_tabs[t * 128 + n2];
    float2 r;
    r.x = v.x * c - v.y * s;   // even: v*cos - v_odd*sin
    r.y = v.y * c + v.x * s;   // odd : v*cos + v_even*sin
    *(float2*)(dst + off) = r;
}

// ---------------- kernel 3: per-chunk S = KR^T @ V (128x128 blocks) ---------
// grid: (BH*NCH, 4), block 256 (16x16), 8x8 per thread
__global__ void k_chunk_kv(const float* __restrict__ V) {
    int bx = blockIdx.x;
    int bh = bx >> 4, ch = bx & 15;
    int m0 = (blockIdx.y >> 1) * 128;
    int n0 = (blockIdx.y & 1) * 128;
    int t0 = ch * CC;

    __shared__ float as[16][128];
    __shared__ float bs[16][128];

    int tid = threadIdx.x;
    int ty = tid >> 4, tx = tid & 15;

    const float* KRp = g_KR + (bh * TT + t0) * NN;
    const float* Vp  = V    + (size_t)(bh * TT + t0) * NN;

    float acc[8][8];
#pragma unroll
    for (int i = 0; i < 8; i++)
#pragma unroll
        for (int j = 0; j < 8; j++) acc[i][j] = 0.f;

    for (int ks = 0; ks < CC; ks += 16) {
#pragma unroll
        for (int l = 0; l < 2; l++) {
            int idx = tid + l * 256;            // 0..511
            int ss = idx >> 5;
            int c4 = (idx & 31) << 2;
            *(float4*)&as[ss][c4] = *(const float4*)(KRp + (ks + ss) * NN + m0 + c4);
            *(float4*)&bs[ss][c4] = *(const float4*)(Vp  + (ks + ss) * NN + n0 + c4);
        }
        __syncthreads();
#pragma unroll
        for (int kk = 0; kk < 16; kk++) {
            float a[8], b[8];
            *(float4*)&a[0] = *(float4*)&as[kk][ty * 8];
            *(float4*)&a[4] = *(float4*)&as[kk][ty * 8 + 4];
            *(float4*)&b[0] = *(float4*)&bs[kk][tx * 8];
            *(float4*)&b[4] = *(float4*)&bs[kk][tx * 8 + 4];
#pragma unroll
            for (int i = 0; i < 8; i++)
#pragma unroll
                for (int j = 0; j < 8; j++)
                    acc[i][j] = fmaf(a[i], b[j], acc[i][j]);
        }
        __syncthreads();
    }

    float* Sp = g_S + (size_t)(bh * NCH + ch) * (NN * NN);
#pragma unroll
    for (int i = 0; i < 8; i++) {
        int row = m0 + ty * 8 + i;
        *(float4*)&Sp[row * NN + n0 + tx * 8]     = *(float4*)&acc[i][0];
        *(float4*)&Sp[row * NN + n0 + tx * 8 + 4] = *(float4*)&acc[i][4];
    }
}

// ---------------- kernel 4: exclusive prefix scan over chunks (in place) ----
__global__ void k_scan() {
    int g = blockIdx.x * blockDim.x + threadIdx.x;    // 24*65536 lanes
    if (g >= BH * NN * NN) return;
    int bh = g >> 16;
    int e  = g & 65535;
    size_t base = (size_t)bh * NCH * (NN * NN) + e;
    float run = 0.f;
#pragma unroll
    for (int i = 0; i < NCH; i++) {
        float v = g_S[base + (size_t)i * (NN * NN)];
        g_S[base + (size_t)i * (NN * NN)] = run;
        run += v;
    }
}

// ---------------- kernel 5: per-chunk output --------------------------------
// Out_i = QR_i @ S_pref_i + strict_tril(QR_i @ KR_i^T) @ V_i
// grid 384, block 512 (ty=tid/32 in [0,16), tx=tid%32), 8x8 acc -> 128x256 tile
#define PS_STRIDE 132
#define AT_STRIDE 132
#define BT_STRIDE 260
#define SMEM_FLOATS (128*PS_STRIDE + 16*AT_STRIDE + 16*BT_STRIDE)

__global__ void k_attn(const float* __restrict__ V, float* __restrict__ out) {
    extern __shared__ float sm[];
    float* Ps = sm;                                   // [128][132]
    float* at = sm + 128 * PS_STRIDE;                 // [16][132]
    float* bt = sm + 128 * PS_STRIDE + 16 * AT_STRIDE;// [16][260]

    int bx = blockIdx.x;
    int bh = bx >> 4, ch = bx & 15;
    int t0 = ch * CC;
    int tid = threadIdx.x;
    int ty = tid >> 5;        // 0..15
    int tx = tid & 31;        // 0..31

    const float* QRp = g_QR + (bh * TT + t0) * NN;
    const float* KRp = g_KR + (bh * TT + t0) * NN;

    // ---- Stage P: P = QR_i @ KR_i^T (128x128), per-thread 8x4 -------------
    float p[8][4];
#pragma unroll
    for (int i = 0; i < 8; i++)
#pragma unroll
        for (int j = 0; j < 4; j++) p[i][j] = 0.f;

    int lr = tid >> 2;             // loader row 0..127
    int lk4 = (tid & 3) << 2;      // loader k offset

    for (int ks = 0; ks < NN; ks += 16) {
        // transpose-load QR slab -> at[kk][r], KR slab -> bt[kk][c]
        float4 va = *(const float4*)(QRp + lr * NN + ks + lk4);
        float4 vb = *(const float4*)(KRp + lr * NN + ks + lk4);
        at[(lk4 + 0) * AT_STRIDE + lr] = va.x;
        at[(lk4 + 1) * AT_STRIDE + lr] = va.y;
        at[(lk4 + 2) * AT_STRIDE + lr] = va.z;
        at[(lk4 + 3) * AT_STRIDE + lr] = va.w;
        bt[(lk4 + 0) * BT_STRIDE + lr] = vb.x;
        bt[(lk4 + 1) * BT_STRIDE + lr] = vb.y;
        bt[(lk4 + 2) * BT_STRIDE + lr] = vb.z;
        bt[(lk4 + 3) * BT_STRIDE + lr] = vb.w;
        __syncthreads();
#pragma unroll
        for (int kk = 0; kk < 16; kk++) {
            float a[8], b4[4];
            *(float4*)&a[0]  = *(float4*)&at[kk * AT_STRIDE + ty * 8];
            *(float4*)&a[4]  = *(float4*)&at[kk * AT_STRIDE + ty * 8 + 4];
            *(float4*)&b4[0] = *(float4*)&bt[kk * BT_STRIDE + tx * 4];
#pragma unroll
            for (int i = 0; i < 8; i++)
#pragma unroll
                for (int j = 0; j < 4; j++)
                    p[i][j] = fmaf(a[i], b4[j], p[i][j]);
        }
        __syncthreads();
    }
    // masked write: keep s < t  (strict lower triangle)
#pragma unroll
    for (int i = 0; i < 8; i++) {
        int r = ty * 8 + i;
#pragma unroll
        for (int j = 0; j < 4; j++) {
            int c = tx * 4 + j;
            Ps[r * PS_STRIDE + c] = (c < r) ? p[i][j] : 0.f;
        }
    }
    __syncthreads();

    // ---- Stage G: acc = QR_i @ S_pref + Ps @ V_i ---------------------------
    float acc[8][8];
#pragma unroll
    for (int i = 0; i < 8; i++)
#pragma unroll
        for (int j = 0; j < 8; j++) acc[i][j] = 0.f;

    // GEMM 1: QR_i (128x256) @ S_pref (256x256)
    const float* Sp = g_S + (size_t)(bh * NCH + ch) * (NN * NN);
    for (int ks = 0; ks < NN; ks += 16) {
        float4 va = *(const float4*)(QRp + lr * NN + ks + lk4);
        at[(lk4 + 0) * AT_STRIDE + lr] = va.x;
        at[(lk4 + 1) * AT_STRIDE + lr] = va.y;
        at[(lk4 + 2) * AT_STRIDE + lr] = va.z;
        at[(lk4 + 3) * AT_STRIDE + lr] = va.w;
#pragma unroll
        for (int l = 0; l < 2; l++) {
            int idx = tid + l * 512;       // 0..1023
            int kk = idx >> 6;
            int c4 = (idx & 63) << 2;
            *(float4*)&bt[kk * BT_STRIDE + c4] =
                *(const float4*)(Sp + (ks + kk) * NN + c4);
        }
        __syncthreads();
#pragma unroll
        for (int kk = 0; kk < 16; kk++) {
            float a[8], b[8];
            *(float4*)&a[0] = *(float4*)&at[kk * AT_STRIDE + ty * 8];
            *(float4*)&a[4] = *(float4*)&at[kk * AT_STRIDE + ty * 8 + 4];
            *(float4*)&b[0] = *(float4*)&bt[kk * BT_STRIDE + tx * 8];
            *(float4*)&b[4] = *(float4*)&bt[kk * BT_STRIDE + tx * 8 + 4];
#pragma unroll
            for (int i = 0; i < 8; i++)
#pragma unroll
                for (int j = 0; j < 8; j++)
                    acc[i][j] = fmaf(a[i], b[j], acc[i][j]);
        }
        __syncthreads();
    }

    // GEMM 2: Ps (128x128, in smem) @ V_i (128x256)
    const float* Vp = V + (size_t)(bh * TT + t0) * NN;
    for (int ks = 0; ks < CC; ks += 16) {
#pragma unroll
        for (int l = 0; l < 2; l++) {
            int idx = tid + l * 512;
            int kk = idx >> 6;
            int c4 = (idx & 63) << 2;
            *(float4*)&bt[kk * BT_STRIDE + c4] =
                *(const float4*)(Vp + (ks + kk) * NN + c4);
        }
        __syncthreads();
#pragma unroll
        for (int kk = 0; kk < 16; kk++) {
            float b[8];
            *(float4*)&b[0] = *(float4*)&bt[kk * BT_STRIDE + tx * 8];
            *(float4*)&b[4] = *(float4*)&bt[kk * BT_STRIDE + tx * 8 + 4];
#pragma unroll
            for (int i = 0; i < 8; i++) {
                float a = Ps[(ty * 8 + i) * PS_STRIDE + ks + kk];
#pragma unroll
                for (int j = 0; j < 8; j++)
                    acc[i][j] = fmaf(a, b[j], acc[i][j]);
            }
        }
        __syncthreads();
    }

    // write output
    float* Op = out + (size_t)(bh * TT + t0) * NN;
#pragma unroll
    for (int i = 0; i < 8; i++) {
        int row = ty * 8 + i;
        *(float4*)&Op[row * NN + tx * 8]     = *(float4*)&acc[i][0];
        *(float4*)&Op[row * NN + tx * 8 + 4] = *(float4*)&acc[i][4];
    }
}

// ---------------- launcher ---------------------------------------------------
extern "C" void kernel_launch(void* const* d_in, const int* in_sizes, int n_in,
                              void* d_out, int out_size) {
    const float* Q = (const float*)d_in[0];
    const float* K = (const float*)d_in[1];
    const float* V = (const float*)d_in[2];
    float* out = (float*)d_out;

    static bool attr_set = false;
    if (!attr_set) {
        cudaFuncSetAttribute(k_attn, cudaFuncAttributeMaxDynamicSharedMemorySize,
                             SMEM_FLOATS * (int)sizeof(float));
        attr_set = true;
    }

    // 1. phase tables (262144 threads)
    k_tables<<<512, 512>>>();
    // 2. RoPE Q,K (2 * 6291456 pairs)
    int rope_total = 2 * BH * TT * (NN / 2);
    k_rope<<<(rope_total + 255) / 256, 256>>>(Q, K);
    // 3. per-chunk KV states
    k_chunk_kv<<<dim3(BH * NCH, 4), 256>>>(V);
    // 4. exclusive scan over chunks
    k_scan<<<(BH * NN * NN) / 256, 256>>>();
    // 5. outputs
    k_attn<<<BH * NCH, 512, SMEM_FLOATS * (int)sizeof(float)>>>(V, out);
}